// round 4
// baseline (speedup 1.0000x reference)
#include <cuda_runtime.h>
#include <math.h>

// ============================================================================
// CKConv via FFT convolution, fused tf32 tensor-core spectrum GEMM.
//   Outf[b,o,f] = Σ_i Xf[b,i,f] · Σ_m Gf[m,f]·W3p[m, i*64+o]    (Kf never stored)
// Hermitian-packed FFTs: two real rows per complex 4096-pt transform.
// ============================================================================

#define LL     2048
#define NFFT   4096
#define HID    128
#define NBINS  2049   // NFFT/2 + 1

// ---- scratch (static __device__ globals; no runtime allocation) ----
__device__ float  d_h2T[HID * LL];         // [m][l]
__device__ float  d_W3p[HID * 4096];       // [m][n'] n' = i*64+o, tf32-rounded
__device__ float2 d_tw4[NFFT];             // e^{-2pi i j / N}
__device__ float2 d_Gf[HID * NFFT];        // [m][f] tf32-rounded, Hermitian-mirrored
__device__ float2 d_Xf[128 * NFFT];        // [b*64+i][f], Hermitian-mirrored
__device__ float2 d_Outf[128 * NBINS];     // [b*64+o][f]

__device__ __forceinline__ float to_tf32(float x) {
    unsigned u;
    asm("cvt.rna.tf32.f32 %0, %1;" : "=r"(u) : "f"(x));
    return __uint_as_float(u);
}

// -------------------------------------------- setup: twiddles + W3 permute --
__global__ void setup_kernel(const float* __restrict__ W3) {
    int idx = blockIdx.x * blockDim.x + threadIdx.x;   // < 128*4096
    if (idx < NFFT) {
        double a = 2.0 * 3.14159265358979323846 * (double)idx / (double)NFFT;
        d_tw4[idx] = make_float2((float)cos(a), (float)(-sin(a)));
    }
    int m  = idx >> 12;
    int np = idx & 4095;
    d_W3p[idx] = to_tf32(W3[(m << 12) + ((np & 63) << 6) + (np >> 6)]);
}

// ------------------------------------------------------------ SIREN stages --
__global__ void gen_h2_kernel(const float* __restrict__ W1,
                              const float* __restrict__ W2) {
    int l = blockIdx.x;     // 0..2047
    int j = threadIdx.x;    // 0..127
    __shared__ float h1[HID];
    float rel = -1.0f + 2.0f * (float)l / 2047.0f;
    h1[j] = sinf(30.0f * rel * W1[j]);
    __syncthreads();
    float acc = 0.0f;
#pragma unroll 16
    for (int m = 0; m < HID; m++)
        acc += h1[m] * W2[m * HID + j];
    d_h2T[j * LL + l] = sinf(30.0f * acc);   // transposed: [m][l]
}

// ------------------------------------------------------- radix-4 FFT core --
__device__ __forceinline__ int rev4(int d) {
    int r = __brev(d) >> 20;
    return ((r & 0x555) << 1) | ((r & 0xAAA) >> 1);
}
__device__ __forceinline__ float2 cmul(float2 a, float2 b) {
    return make_float2(a.x * b.x - a.y * b.y, a.x * b.y + a.y * b.x);
}
__device__ __forceinline__ void fft4_core(float2* buf) {
#pragma unroll
    for (int st = 0; st < 6; st++) {
        int q = 1 << (2 * st);
        int tstep = NFFT >> (2 * st + 2);
        __syncthreads();
#pragma unroll
        for (int k = 0; k < 2; k++) {
            int bf = threadIdx.x + (k << 9);
            int j  = bf & (q - 1);
            int i0 = ((bf >> (2 * st)) << (2 * st + 2)) + j;
            float2 x0 = buf[i0];
            float2 x1 = buf[i0 + q];
            float2 x2 = buf[i0 + 2 * q];
            float2 x3 = buf[i0 + 3 * q];
            float2 u1 = cmul(x1, d_tw4[j * tstep]);
            float2 u2 = cmul(x2, d_tw4[2 * j * tstep]);
            float2 u3 = cmul(x3, d_tw4[3 * j * tstep]);
            float2 a  = make_float2(x0.x + u2.x, x0.y + u2.y);
            float2 b  = make_float2(x0.x - u2.x, x0.y - u2.y);
            float2 c  = make_float2(u1.x + u3.x, u1.y + u3.y);
            float2 dd = make_float2(u1.x - u3.x, u1.y - u3.y);
            buf[i0]         = make_float2(a.x + c.x,  a.y + c.y);
            buf[i0 + q]     = make_float2(b.x + dd.y, b.y - dd.x);
            buf[i0 + 2 * q] = make_float2(a.x - c.x,  a.y - c.y);
            buf[i0 + 3 * q] = make_float2(b.x - dd.y, b.y + dd.x);
        }
    }
    __syncthreads();
}

// ---------------------------- forward FFTs, two real rows packed per block --
// blocks 0..63: g rows (m=2b, 2b+1), time-reversed h2. blocks 64..127: x rows.
__global__ void fft_gx_kernel(const float* __restrict__ x) {
    __shared__ float2 buf[NFFT];
    int blk = blockIdx.x;
    bool isg = blk < 64;
    int r0 = isg ? 2 * blk : 2 * (blk - 64);
    for (int d = threadIdx.x; d < NFFT; d += 512) {
        int src = rev4(d);
        float va = 0.0f, vb = 0.0f;
        if (src < LL) {
            if (isg) {
                va = d_h2T[r0 * LL + (LL - 1 - src)];
                vb = d_h2T[(r0 + 1) * LL + (LL - 1 - src)];
            } else {
                va = x[r0 * LL + src];
                vb = x[(r0 + 1) * LL + src];
            }
        }
        buf[d] = make_float2(va, vb);
    }
    fft4_core(buf);
    // unpack: A = (Z[f]+conj(Z[N-f]))/2 ; B = (Z[f]-conj(Z[N-f]))/(2i)
    for (int f = threadIdx.x; f <= 2048; f += 512) {
        float2 Zf = buf[f];
        float2 Zc = buf[(NFFT - f) & (NFFT - 1)];
        float2 A = make_float2((Zf.x + Zc.x) * 0.5f, (Zf.y - Zc.y) * 0.5f);
        float2 B = make_float2((Zf.y + Zc.y) * 0.5f, (Zc.x - Zf.x) * 0.5f);
        if (isg) {
            A = make_float2(to_tf32(A.x), to_tf32(A.y));
            B = make_float2(to_tf32(B.x), to_tf32(B.y));
            d_Gf[r0 * NFFT + f]       = A;
            d_Gf[(r0 + 1) * NFFT + f] = B;
            if (f > 0 && f < 2048) {
                d_Gf[r0 * NFFT + NFFT - f]       = make_float2(A.x, -A.y);
                d_Gf[(r0 + 1) * NFFT + NFFT - f] = make_float2(B.x, -B.y);
            }
        } else {
            d_Xf[r0 * NFFT + f]       = A;
            d_Xf[(r0 + 1) * NFFT + f] = B;
            if (f > 0 && f < 2048) {
                d_Xf[r0 * NFFT + NFFT - f]       = make_float2(A.x, -A.y);
                d_Xf[(r0 + 1) * NFFT + NFFT - f] = make_float2(B.x, -B.y);
            }
        }
    }
}

// ----------------------- k45: fused kernel-spectrum GEMM + per-bin mixing --
#define MMA_TF32(C, A, B0, B1)                                              \
    asm volatile("mma.sync.aligned.m16n8k8.row.col.f32.tf32.tf32.f32 "      \
        "{%0,%1,%2,%3}, {%4,%5,%6,%7}, {%8,%9}, {%0,%1,%2,%3};"             \
        : "+f"(C[0]), "+f"(C[1]), "+f"(C[2]), "+f"(C[3])                    \
        : "r"(A[0]), "r"(A[1]), "r"(A[2]), "r"(A[3]), "r"(B0), "r"(B1))

__global__ void __launch_bounds__(256) k45_kernel() {
    __shared__ float2 Xs[128 * 16];            // [b*64+i][f-local]
    const int f0   = blockIdx.x * 16;          // grid 129: f0 <= 2048
    const int lane = threadIdx.x & 31;
    const int warp = threadIdx.x >> 5;         // 0..7
    const int g    = lane >> 2;                // 0..7
    const int tg   = lane & 3;                 // 0..3
    const int obase = warp * 8;

    for (int idx = threadIdx.x; idx < 128 * 16; idx += 256) {
        int row = idx >> 4, ff = idx & 15;
        Xs[idx] = d_Xf[row * NFFT + f0 + ff];
    }
    __syncthreads();

    // Hoist A fragments: Gf[k][f-tile], all 16 k-steps, complex.
    unsigned aR[16][4], aI[16][4];
#pragma unroll
    for (int k0 = 0; k0 < 16; k0++) {
        int kk = k0 * 8;
        float2 v0 = d_Gf[(kk + tg)     * NFFT + f0 + g];
        float2 v1 = d_Gf[(kk + tg)     * NFFT + f0 + g + 8];
        float2 v2 = d_Gf[(kk + tg + 4) * NFFT + f0 + g];
        float2 v3 = d_Gf[(kk + tg + 4) * NFFT + f0 + g + 8];
        aR[k0][0] = __float_as_uint(v0.x); aI[k0][0] = __float_as_uint(v0.y);
        aR[k0][1] = __float_as_uint(v1.x); aI[k0][1] = __float_as_uint(v1.y);
        aR[k0][2] = __float_as_uint(v2.x); aI[k0][2] = __float_as_uint(v2.y);
        aR[k0][3] = __float_as_uint(v3.x); aI[k0][3] = __float_as_uint(v3.y);
    }

    float oR[2][2][2] = {}, oI[2][2][2] = {};  // [b][rr][cc]

    for (int i = 0; i < 64; i++) {
        float cR[4] = {0.f, 0.f, 0.f, 0.f};
        float cI[4] = {0.f, 0.f, 0.f, 0.f};
        const float* Bp = d_W3p + i * 64 + obase + g;
#pragma unroll
        for (int k0 = 0; k0 < 16; k0++) {
            unsigned b0 = __float_as_uint(__ldg(Bp + (k0 * 8 + tg)     * 4096));
            unsigned b1 = __float_as_uint(__ldg(Bp + (k0 * 8 + tg + 4) * 4096));
            MMA_TF32(cR, aR[k0], b0, b1);
            MMA_TF32(cI, aI[k0], b0, b1);
        }
        // epilogue: Out[b,o,f] += Xf[b,i,f] * Kf
#pragma unroll
        for (int rr = 0; rr < 2; rr++) {
            int flocal = g + rr * 8;
#pragma unroll
            for (int b = 0; b < 2; b++) {
                float2 xv = Xs[(b * 64 + i) * 16 + flocal];
#pragma unroll
                for (int cc = 0; cc < 2; cc++) {
                    float kr = cR[rr * 2 + cc], ki = cI[rr * 2 + cc];
                    oR[b][rr][cc] += xv.x * kr - xv.y * ki;
                    oI[b][rr][cc] += xv.x * ki + xv.y * kr;
                }
            }
        }
    }
    // store Outf
#pragma unroll
    for (int rr = 0; rr < 2; rr++) {
        int f = f0 + g + rr * 8;
        if (f < NBINS) {
#pragma unroll
            for (int b = 0; b < 2; b++)
#pragma unroll
                for (int cc = 0; cc < 2; cc++) {
                    int o = obase + tg * 2 + cc;
                    d_Outf[(b * 64 + o) * NBINS + f] =
                        make_float2(oR[b][rr][cc], oI[b][rr][cc]);
                }
        }
    }
}

// ------------------- inverse FFT: two real output rows packed per block ----
__global__ void fft_inv_kernel(float* __restrict__ out) {
    __shared__ float2 buf[NFFT];
    int t0 = 2 * blockIdx.x;   // rows b*64+o
    const float2* O0 = d_Outf + (size_t)t0 * NBINS;
    const float2* O1 = d_Outf + (size_t)(t0 + 1) * NBINS;
    for (int d = threadIdx.x; d < NFFT; d += 512) {
        int src = rev4(d);
        float2 v;
        if (src <= 2048) {
            float2 a = O0[src], b = O1[src];
            v = make_float2(a.x - b.y, -a.y - b.x);       // conj(O0 + i*O1)
        } else {
            int s = NFFT - src;
            float2 a = O0[s], b = O1[s];
            v = make_float2(a.x + b.y, a.y - b.x);        // conj of Hermitian ext
        }
        buf[d] = v;
    }
    fft4_core(buf);
    const float inv = 1.0f / (float)NFFT;
    for (int n = threadIdx.x; n < LL; n += 512) {
        out[t0 * LL + n]       =  buf[n].x * inv;
        out[(t0 + 1) * LL + n] = -buf[n].y * inv;
    }
}

// ============================================================================
extern "C" void kernel_launch(void* const* d_in, const int* in_sizes, int n_in,
                              void* d_out, int out_size) {
    (void)in_sizes; (void)n_in; (void)out_size;
    const float* x  = (const float*)d_in[0];
    const float* W1 = (const float*)d_in[1];
    const float* W2 = (const float*)d_in[2];
    const float* W3 = (const float*)d_in[3];
    float* out = (float*)d_out;

    setup_kernel<<<2048, 256>>>(W3);
    gen_h2_kernel<<<2048, 128>>>(W1, W2);
    fft_gx_kernel<<<128, 512>>>(x);
    k45_kernel<<<129, 256>>>();
    fft_inv_kernel<<<64, 512>>>(out);
}

// round 5
// speedup vs baseline: 2.3696x; 2.3696x over previous
#include <cuda_runtime.h>
#include <math.h>

// ============================================================================
// CKConv via FFT convolution, fused tf32 tensor-core spectrum GEMM.
//   Outf[b,o,f] = Σ_i Xf[b,i,f] · Σ_m Gf[m,f]·W3p[m, i*64+o]   (Kf never stored)
// Hermitian-packed FFTs; k45 streams W3p panels through double-buffered smem.
// ============================================================================

#define LL     2048
#define NFFT   4096
#define HID    128
#define NBINS  2049   // NFFT/2 + 1

// ---- scratch (static __device__ globals; no runtime allocation) ----
__device__ float  d_h2T[HID * LL];         // [m][l]
__device__ float  d_W3p[HID * 4096];       // [m][n'] n' = i*64+o, tf32-rounded
__device__ float2 d_tw4[NFFT];             // e^{-2pi i j / N}
__device__ float2 d_Gf[HID * NFFT];        // [m][f] tf32-rounded, mirrored
__device__ float2 d_Xf[128 * NFFT];        // [b*64+i][f], mirrored
__device__ float2 d_Outf[128 * NBINS];     // [b*64+o][f]

__device__ __forceinline__ float to_tf32(float x) {
    unsigned u;
    asm("cvt.rna.tf32.f32 %0, %1;" : "=r"(u) : "f"(x));
    return __uint_as_float(u);
}

// -------------------------------------------- setup: twiddles + W3 permute --
__global__ void setup_kernel(const float* __restrict__ W3) {
    int idx = blockIdx.x * blockDim.x + threadIdx.x;   // < 128*4096
    if (idx < NFFT) {
        double a = 2.0 * 3.14159265358979323846 * (double)idx / (double)NFFT;
        d_tw4[idx] = make_float2((float)cos(a), (float)(-sin(a)));
    }
    int m  = idx >> 12;
    int np = idx & 4095;
    d_W3p[idx] = to_tf32(W3[(m << 12) + ((np & 63) << 6) + (np >> 6)]);
}

// ------------------------------------------------------------ SIREN stages --
__global__ void gen_h2_kernel(const float* __restrict__ W1,
                              const float* __restrict__ W2) {
    int l = blockIdx.x;     // 0..2047
    int j = threadIdx.x;    // 0..127
    __shared__ float h1[HID];
    float rel = -1.0f + 2.0f * (float)l / 2047.0f;
    h1[j] = sinf(30.0f * rel * W1[j]);
    __syncthreads();
    float acc = 0.0f;
#pragma unroll 16
    for (int m = 0; m < HID; m++)
        acc += h1[m] * W2[m * HID + j];
    d_h2T[j * LL + l] = sinf(30.0f * acc);   // transposed: [m][l]
}

// ------------------------------------------------------- radix-4 FFT core --
__device__ __forceinline__ int rev4(int d) {
    int r = __brev(d) >> 20;
    return ((r & 0x555) << 1) | ((r & 0xAAA) >> 1);
}
__device__ __forceinline__ float2 cmul(float2 a, float2 b) {
    return make_float2(a.x * b.x - a.y * b.y, a.x * b.y + a.y * b.x);
}
__device__ __forceinline__ void fft4_core(float2* buf) {
#pragma unroll
    for (int st = 0; st < 6; st++) {
        int q = 1 << (2 * st);
        int tstep = NFFT >> (2 * st + 2);
        __syncthreads();
#pragma unroll
        for (int k = 0; k < 2; k++) {
            int bf = threadIdx.x + (k << 9);
            int j  = bf & (q - 1);
            int i0 = ((bf >> (2 * st)) << (2 * st + 2)) + j;
            float2 x0 = buf[i0];
            float2 x1 = buf[i0 + q];
            float2 x2 = buf[i0 + 2 * q];
            float2 x3 = buf[i0 + 3 * q];
            float2 u1 = cmul(x1, d_tw4[j * tstep]);
            float2 u2 = cmul(x2, d_tw4[2 * j * tstep]);
            float2 u3 = cmul(x3, d_tw4[3 * j * tstep]);
            float2 a  = make_float2(x0.x + u2.x, x0.y + u2.y);
            float2 b  = make_float2(x0.x - u2.x, x0.y - u2.y);
            float2 c  = make_float2(u1.x + u3.x, u1.y + u3.y);
            float2 dd = make_float2(u1.x - u3.x, u1.y - u3.y);
            buf[i0]         = make_float2(a.x + c.x,  a.y + c.y);
            buf[i0 + q]     = make_float2(b.x + dd.y, b.y - dd.x);
            buf[i0 + 2 * q] = make_float2(a.x - c.x,  a.y - c.y);
            buf[i0 + 3 * q] = make_float2(b.x - dd.y, b.y + dd.x);
        }
    }
    __syncthreads();
}

// ---------------------------- forward FFTs, two real rows packed per block --
__global__ void fft_gx_kernel(const float* __restrict__ x) {
    __shared__ float2 buf[NFFT];
    int blk = blockIdx.x;
    bool isg = blk < 64;
    int r0 = isg ? 2 * blk : 2 * (blk - 64);
    for (int d = threadIdx.x; d < NFFT; d += 512) {
        int src = rev4(d);
        float va = 0.0f, vb = 0.0f;
        if (src < LL) {
            if (isg) {
                va = d_h2T[r0 * LL + (LL - 1 - src)];
                vb = d_h2T[(r0 + 1) * LL + (LL - 1 - src)];
            } else {
                va = x[r0 * LL + src];
                vb = x[(r0 + 1) * LL + src];
            }
        }
        buf[d] = make_float2(va, vb);
    }
    fft4_core(buf);
    for (int f = threadIdx.x; f <= 2048; f += 512) {
        float2 Zf = buf[f];
        float2 Zc = buf[(NFFT - f) & (NFFT - 1)];
        float2 A = make_float2((Zf.x + Zc.x) * 0.5f, (Zf.y - Zc.y) * 0.5f);
        float2 B = make_float2((Zf.y + Zc.y) * 0.5f, (Zc.x - Zf.x) * 0.5f);
        if (isg) {
            A = make_float2(to_tf32(A.x), to_tf32(A.y));
            B = make_float2(to_tf32(B.x), to_tf32(B.y));
            d_Gf[r0 * NFFT + f]       = A;
            d_Gf[(r0 + 1) * NFFT + f] = B;
            if (f > 0 && f < 2048) {
                d_Gf[r0 * NFFT + NFFT - f]       = make_float2(A.x, -A.y);
                d_Gf[(r0 + 1) * NFFT + NFFT - f] = make_float2(B.x, -B.y);
            }
        } else {
            d_Xf[r0 * NFFT + f]       = A;
            d_Xf[(r0 + 1) * NFFT + f] = B;
            if (f > 0 && f < 2048) {
                d_Xf[r0 * NFFT + NFFT - f]       = make_float2(A.x, -A.y);
                d_Xf[(r0 + 1) * NFFT + NFFT - f] = make_float2(B.x, -B.y);
            }
        }
    }
}

// ----------------------- k45: fused kernel-spectrum GEMM + per-bin mixing --
#define MMA_TF32(C, A, B0, B1)                                              \
    asm volatile("mma.sync.aligned.m16n8k8.row.col.f32.tf32.tf32.f32 "      \
        "{%0,%1,%2,%3}, {%4,%5,%6,%7}, {%8,%9}, {%0,%1,%2,%3};"             \
        : "+f"(C[0]), "+f"(C[1]), "+f"(C[2]), "+f"(C[3])                    \
        : "r"(A[0]), "r"(A[1]), "r"(A[2]), "r"(A[3]), "r"(B0), "r"(B1))

#define CP16(dst_u32, src_ptr)                                              \
    asm volatile("cp.async.cg.shared.global [%0], [%1], 16;"                \
                 :: "r"(dst_u32), "l"(src_ptr))

#define BPAD   72                     // row stride in floats (bank-safe)
#define PANEL  (HID * BPAD)           // 9216 floats per buffer
#define K45_SMEM (128 * 16 * 8 + 2 * PANEL * 4)   // Xs + 2 panels = 90112 B

__global__ void __launch_bounds__(256) k45_kernel() {
    extern __shared__ float smem[];
    float2* Xs = (float2*)smem;                 // [128][16]
    float*  Bs = smem + 128 * 16 * 2;           // [2][128][BPAD]

    const int f0   = blockIdx.x * 16;           // grid 129: f0 <= 2048
    const int tid  = threadIdx.x;
    const int lane = tid & 31;
    const int warp = tid >> 5;                  // 0..7
    const int g    = lane >> 2;                 // 0..7
    const int tg   = lane & 3;                  // 0..3
    const int obase = warp * 8;

    // ---- panel prefetch helper: W3p[0:128, i*64:(i+1)*64] -> Bs[buf] ----
    // 2048 float4 per panel; thread does 8, coalesced (16 threads per row).
    unsigned bs_base = (unsigned)__cvta_generic_to_shared(Bs);
#define LOAD_PANEL(i_, buf_)                                                \
    {                                                                       \
        const float* srcb = d_W3p + (i_) * 64;                              \
        unsigned dstb = bs_base + (buf_) * (PANEL * 4);                     \
        _Pragma("unroll")                                                   \
        for (int r8 = 0; r8 < 8; r8++) {                                    \
            int idx = tid + (r8 << 8);          /* 0..2047 */               \
            int row = idx >> 4, c4 = idx & 15;                              \
            CP16(dstb + (row * BPAD + c4 * 4) * 4,                          \
                 srcb + row * 4096 + c4 * 4);                               \
        }                                                                   \
    }

    // ---- Xs load + A-fragment hoist (overlap with first panel cp.async) --
    LOAD_PANEL(0, 0);
    asm volatile("cp.async.commit_group;");

    for (int idx = tid; idx < 128 * 16; idx += 256) {
        int row = idx >> 4, ff = idx & 15;
        Xs[idx] = d_Xf[row * NFFT + f0 + ff];
    }

    unsigned aR[16][4], aI[16][4];
#pragma unroll
    for (int k0 = 0; k0 < 16; k0++) {
        int kk = k0 * 8;
        float2 v0 = d_Gf[(kk + tg)     * NFFT + f0 + g];
        float2 v1 = d_Gf[(kk + tg)     * NFFT + f0 + g + 8];
        float2 v2 = d_Gf[(kk + tg + 4) * NFFT + f0 + g];
        float2 v3 = d_Gf[(kk + tg + 4) * NFFT + f0 + g + 8];
        aR[k0][0] = __float_as_uint(v0.x); aI[k0][0] = __float_as_uint(v0.y);
        aR[k0][1] = __float_as_uint(v1.x); aI[k0][1] = __float_as_uint(v1.y);
        aR[k0][2] = __float_as_uint(v2.x); aI[k0][2] = __float_as_uint(v2.y);
        aR[k0][3] = __float_as_uint(v3.x); aI[k0][3] = __float_as_uint(v3.y);
    }

    float oR[2][2][2] = {}, oI[2][2][2] = {};   // [b][rr][cc]

    asm volatile("cp.async.wait_group 0;");
    __syncthreads();

    for (int i = 0; i < 64; i++) {
        int cur = i & 1;
        if (i < 63) {                            // prefetch next panel
            LOAD_PANEL(i + 1, cur ^ 1);
            asm volatile("cp.async.commit_group;");
        }

        float cR[4] = {0.f, 0.f, 0.f, 0.f};
        float cI[4] = {0.f, 0.f, 0.f, 0.f};
        const float* Bp = Bs + cur * PANEL + obase + g;
#pragma unroll
        for (int k0 = 0; k0 < 16; k0++) {
            unsigned b0 = __float_as_uint(Bp[(k0 * 8 + tg)     * BPAD]);
            unsigned b1 = __float_as_uint(Bp[(k0 * 8 + tg + 4) * BPAD]);
            MMA_TF32(cR, aR[k0], b0, b1);
            MMA_TF32(cI, aI[k0], b0, b1);
        }
        // epilogue: Out[b,o,f] += Xf[b,i,f] * Kf
#pragma unroll
        for (int rr = 0; rr < 2; rr++) {
            int flocal = g + rr * 8;
#pragma unroll
            for (int b = 0; b < 2; b++) {
                float2 xv = Xs[(b * 64 + i) * 16 + flocal];
#pragma unroll
                for (int cc = 0; cc < 2; cc++) {
                    float kr = cR[rr * 2 + cc], ki = cI[rr * 2 + cc];
                    oR[b][rr][cc] += xv.x * kr - xv.y * ki;
                    oI[b][rr][cc] += xv.x * ki + xv.y * kr;
                }
            }
        }

        asm volatile("cp.async.wait_group 0;");
        __syncthreads();
    }

    // ---- store Outf ----
#pragma unroll
    for (int rr = 0; rr < 2; rr++) {
        int f = f0 + g + rr * 8;
        if (f < NBINS) {
#pragma unroll
            for (int b = 0; b < 2; b++)
#pragma unroll
                for (int cc = 0; cc < 2; cc++) {
                    int o = obase + tg * 2 + cc;
                    d_Outf[(b * 64 + o) * NBINS + f] =
                        make_float2(oR[b][rr][cc], oI[b][rr][cc]);
                }
        }
    }
}

// ------------------- inverse FFT: two real output rows packed per block ----
__global__ void fft_inv_kernel(float* __restrict__ out) {
    __shared__ float2 buf[NFFT];
    int t0 = 2 * blockIdx.x;
    const float2* O0 = d_Outf + (size_t)t0 * NBINS;
    const float2* O1 = d_Outf + (size_t)(t0 + 1) * NBINS;
    for (int d = threadIdx.x; d < NFFT; d += 512) {
        int src = rev4(d);
        float2 v;
        if (src <= 2048) {
            float2 a = O0[src], b = O1[src];
            v = make_float2(a.x - b.y, -a.y - b.x);
        } else {
            int s = NFFT - src;
            float2 a = O0[s], b = O1[s];
            v = make_float2(a.x + b.y, a.y - b.x);
        }
        buf[d] = v;
    }
    fft4_core(buf);
    const float inv = 1.0f / (float)NFFT;
    for (int n = threadIdx.x; n < LL; n += 512) {
        out[t0 * LL + n]       =  buf[n].x * inv;
        out[(t0 + 1) * LL + n] = -buf[n].y * inv;
    }
}

// ============================================================================
extern "C" void kernel_launch(void* const* d_in, const int* in_sizes, int n_in,
                              void* d_out, int out_size) {
    (void)in_sizes; (void)n_in; (void)out_size;
    const float* x  = (const float*)d_in[0];
    const float* W1 = (const float*)d_in[1];
    const float* W2 = (const float*)d_in[2];
    const float* W3 = (const float*)d_in[3];
    float* out = (float*)d_out;

    cudaFuncSetAttribute(k45_kernel,
                         cudaFuncAttributeMaxDynamicSharedMemorySize, K45_SMEM);

    setup_kernel<<<2048, 256>>>(W3);
    gen_h2_kernel<<<2048, 128>>>(W1, W2);
    fft_gx_kernel<<<128, 512>>>(x);
    k45_kernel<<<129, 256, K45_SMEM>>>();
    fft_inv_kernel<<<64, 512>>>(out);
}